// round 14
// baseline (speedup 1.0000x reference)
#include <cuda_runtime.h>
#include <cstdint>
#include <cstddef>

// SpanRepresentation: out[b, s, :] = concat(x[b,start,:], x[b,end,:], wemb[wid,:])
// B=16, L=512, D=768, W=8, WD=64, NS=4068. Spans ordered by width 1..8, then start.
//
// R14: R12 shape (one CTA per output row, 65088 CTAs, 128 threads) but the row is
// assembled in SMEM and emitted as ONE 6400-byte cp.async.bulk store per CTA.
// Purpose: remove all per-thread STG wavefronts from the L1tex global path
// (which co-binds with DRAM at ~76%) while keeping full-chip store concurrency
// (the thing R7's 1024-CTA TMA variant lost). Disambiguates L1-bound vs
// DRAM-write-ceiling.

constexpr int B    = 16;
constexpr int L    = 512;
constexpr int D    = 768;
constexpr int WD   = 64;
constexpr int NS   = 4068;

constexpr int D4   = D / 4;              // 192
constexpr int WD4  = WD / 4;             // 16
constexpr int ROW4 = (2 * D + WD) / 4;   // 400 float4 = 6400 B per output row

__global__ __launch_bounds__(128, 16)
void span_repr_tma_kernel(const float4* __restrict__ x,      // [B, L, D/4]
                          const float4* __restrict__ wemb,   // [8, WD/4]
                          float4* __restrict__ out)          // [B*NS, ROW4]
{
    __shared__ float4 srow[ROW4];        // 6400 B staging for this output row

    const int row = blockIdx.x;
    const int b   = row / NS;
    const int s   = row - b * NS;
    const int tid = threadIdx.x;

    // width bucket (block-uniform, 7 compares)
    int wid = 0;
    wid += (s >= 512);
    wid += (s >= 1023);
    wid += (s >= 1533);
    wid += (s >= 2042);
    wid += (s >= 2550);
    wid += (s >= 3057);
    wid += (s >= 3563);
    const int off   = 512 * wid - (wid * (wid - 1)) / 2;
    const int start = s - off;
    const int end   = start + wid;

    const float4* __restrict__ xs = x    + ((size_t)b * L + start) * D4;
    const float4* __restrict__ xe = x    + ((size_t)b * L + end)   * D4;
    const float4* __restrict__ wf = wemb + (size_t)wid * WD4;

    // ---- issue all loads first (MLP 4), then stage into SMEM via crossbar ----
    const float4 v0 = __ldg(&xs[tid]);                                   // [0,128)
    const float4 v1 = (tid < 64) ? __ldg(&xs[tid + 128])                 // [128,256)
                                 : __ldg(&xe[tid + 128 - D4]);
    const float4 v2 = __ldg(&xe[tid + 256 - D4]);                        // [256,384)
    float4 v3;
    if (tid < WD4) v3 = __ldg(&wf[tid]);                                 // [384,400)

    srow[tid]       = v0;
    srow[tid + 128] = v1;
    srow[tid + 256] = v2;
    if (tid < WD4) srow[tid + 384] = v3;
    __syncthreads();

    // ---- one bulk store pushes the whole row (no per-thread STG wavefronts) ----
    if (tid == 0) {
        asm volatile("fence.proxy.async.shared::cta;" ::: "memory");
        const uint32_t src = (uint32_t)__cvta_generic_to_shared(srow);
        void* dst = (void*)(out + (size_t)row * ROW4);
        asm volatile("cp.async.bulk.global.shared::cta.bulk_group [%0], [%1], %2;"
                     :: "l"(dst), "r"(src), "r"(ROW4 * 16) : "memory");
        asm volatile("cp.async.bulk.commit_group;" ::: "memory");
        asm volatile("cp.async.bulk.wait_group 0;" ::: "memory");  // smem safe to free
    }
}

extern "C" void kernel_launch(void* const* d_in, const int* in_sizes, int n_in,
                              void* d_out, int out_size)
{
    const float4* x    = (const float4*)d_in[0];   // [16, 512, 768] fp32
    const float4* wemb = (const float4*)d_in[1];   // [8, 64] fp32
    float4* out        = (float4*)d_out;           // [16, 4068, 1600] fp32

    (void)in_sizes; (void)n_in; (void)out_size;

    dim3 grid(B * NS);   // 65088 CTAs, one output row each
    dim3 block(128);
    span_repr_tma_kernel<<<grid, block>>>(x, wemb, out);
}